// round 7
// baseline (speedup 1.0000x reference)
#include <cuda_runtime.h>
#include <cuda_bf16.h>
#include <cstdint>

// ---------------------------------------------------------------------------
// B=16, R=64, NOBJ=32, SIZE=64
//   conv1(2->64,5x5)+pool2 -> g_x1 (1024,64,30,30)   [prefix-sum + class tables]
//   conv2(64->32,5x5)+pool2+mean -> g_feat (1024,32) [f32x2, sliding-window]
//   fc(32->512)+relu -> out (1024,512)
// NOTE: harness PTX target is compute_103 (no 'a') -> tcgen05 is NOT usable.
// ---------------------------------------------------------------------------

#define NPAIR 1024
#define X1_PER_PAIR (64*30*30)   // 57600

__device__ float g_P[64*2*36];
__device__ float g_x1[(size_t)NPAIR * X1_PER_PAIR];
__device__ float g_feat[NPAIR * 32];

typedef unsigned long long u64;

__device__ __forceinline__ u64 pack2(float lo, float hi) {
    u64 r; asm("mov.b64 %0, {%1, %2};" : "=l"(r) : "f"(lo), "f"(hi)); return r;
}
__device__ __forceinline__ void unpack2(float& lo, float& hi, u64 v) {
    asm("mov.b64 {%0, %1}, %2;" : "=f"(lo), "=f"(hi) : "l"(v));
}
__device__ __forceinline__ void fma2(u64& d, u64 a, u64 b) {
    asm("fma.rn.f32x2 %0, %1, %2, %0;" : "+l"(d) : "l"(a), "l"(b));
}

// ---------------------------------------------------------------------------
// Kernel 1: 2-D prefix sums of conv1 weights. 128 threads = (co,ci).
// ---------------------------------------------------------------------------
__global__ void k_prefix(const float* __restrict__ conv1_w) {
    int t = threadIdx.x;
    if (t >= 128) return;
    const float* w = conv1_w + t * 25;
    float P[6][6];
#pragma unroll
    for (int i = 0; i < 6; ++i) { P[0][i] = 0.f; P[i][0] = 0.f; }
#pragma unroll
    for (int j = 1; j <= 5; ++j)
#pragma unroll
        for (int i = 1; i <= 5; ++i)
            P[j][i] = w[(j-1)*5 + (i-1)] + P[j-1][i] + P[j][i-1] - P[j-1][i-1];
#pragma unroll
    for (int j = 0; j < 6; ++j)
#pragma unroll
        for (int i = 0; i < 6; ++i)
            g_P[t*36 + j*6 + i] = P[j][i];
}

// ---------------------------------------------------------------------------
// Kernel 2: sp + conv1 + bias + maxpool2 via per-axis clamp classes (R2, kept).
// ---------------------------------------------------------------------------
#define MAXCLS 16
struct SpShm {
    float sP[4608];
    float T[2][64*128];
    float sB[64];
    int   xcls[2][64], ycls[2][64];
    int   xpl[2][MAXCLS], xph[2][MAXCLS];
    int   ypl[2][MAXCLS], yph[2][MAXCLS];
    int   nx[2], ny[2];
    int   rxlo[2], rxhi[2], rylo[2], ryhi[2];
};
#define SP_SMEM ((int)sizeof(SpShm))

__global__ void __launch_bounds__(256, 2)
k_sp_conv1(const float* __restrict__ bboxes,
           const int*   __restrict__ pairs,
           const float* __restrict__ conv1_b) {
    extern __shared__ char smraw[];
    SpShm* S = (SpShm*)smraw;

    int n = blockIdx.x, tid = threadIdx.x;
    for (int i = tid; i < 4608; i += 256) S->sP[i] = g_P[i];
    if (tid < 64) S->sB[tid] = conv1_b[tid];

    if (tid == 0) {
        int b = n >> 6, r = n & 63;
        int o0 = pairs[(b*64 + r)*2 + 0];
        int o1 = pairs[(b*64 + r)*2 + 1];
        const float* A  = bboxes + ((size_t)b*32 + o0)*4;
        const float* Bx = bboxes + ((size_t)b*32 + o1)*4;
        float ux1 = fminf(A[0], Bx[0]), uy1 = fminf(A[1], Bx[1]);
        float ux2 = fmaxf(A[2], Bx[2]), uy2 = fmaxf(A[3], Bx[3]);
        float uw = fmaxf(ux2 - ux1, 1e-6f), uh = fmaxf(uy2 - uy1, 1e-6f);
        const float* bx[2] = {A, Bx};
#pragma unroll
        for (int ci = 0; ci < 2; ++ci) {
            float x1 = (bx[ci][0] - ux1) / uw * 64.0f;
            float y1 = (bx[ci][1] - uy1) / uh * 64.0f;
            float x2 = (bx[ci][2] - ux1) / uw * 64.0f;
            float y2 = (bx[ci][3] - uy1) / uh * 64.0f;
            S->rxlo[ci] = max(0,  (int)ceilf (x1 - 0.5f));
            S->rxhi[ci] = min(63, (int)floorf(x2 - 0.5f));
            S->rylo[ci] = max(0,  (int)ceilf (y1 - 0.5f));
            S->ryhi[ci] = min(63, (int)floorf(y2 - 0.5f));
        }
    }
    __syncthreads();

    if (tid < 4) {
        int ci = tid >> 1, ax = tid & 1;
        int rlo = ax ? S->rylo[ci] : S->rxlo[ci];
        int rhi = ax ? S->ryhi[ci] : S->rxhi[ci];
        int* cls  = ax ? S->ycls[ci] : S->xcls[ci];
        int* lstL = ax ? S->ypl[ci]  : S->xpl[ci];
        int* lstH = ax ? S->yph[ci]  : S->xph[ci];
        int keys[MAXCLS];
        int nc = 0;
        for (int v = 0; v < 60; ++v) {
            int lo = max(0, rlo - v), hi = min(4, rhi - v);
            int key = (hi >= lo) ? (lo * 6 + hi) : 99;
            int id = -1;
            for (int j = 0; j < nc; ++j) if (keys[j] == key) { id = j; break; }
            if (id < 0) {
                id = nc; keys[nc] = key;
                lstL[nc] = (hi >= lo) ? lo : 1;
                lstH[nc] = (hi >= lo) ? hi : 0;
                ++nc;
            }
            cls[v] = id;
        }
        if (ax) S->ny[ci] = nc; else S->nx[ci] = nc;
    }
    __syncthreads();

#pragma unroll
    for (int ci = 0; ci < 2; ++ci) {
        int nxv = S->nx[ci], nyv = S->ny[ci];
        int ncls = nxv * nyv, tot = 64 * ncls;
        for (int i = tid; i < tot; i += 256) {
            int co = i / ncls, c = i - co * ncls;
            int cy = c / nxv, cx = c - cy * nxv;
            int xl = S->xpl[ci][cx], xh = S->xph[ci][cx];
            int yl = S->ypl[ci][cy], yh = S->yph[ci][cy];
            float v = 0.f;
            if (xh >= xl && yh >= yl) {
                const float* P = S->sP + (co*2 + ci)*36;
                v = P[(yh+1)*6 + (xh+1)] - P[yl*6 + (xh+1)]
                  - P[(yh+1)*6 + xl]     + P[yl*6 + xl];
            }
            S->T[ci][co*128 + c] = v;
        }
    }
    __syncthreads();

    int nx0 = S->nx[0], nx1 = S->nx[1];
    for (int pix = tid; pix < 900; pix += 256) {
        int py = pix / 30, px = pix - py*30;
        int y = 2*py, x = 2*px;
        int c0[4], c1[4];
        {
            int a0 = S->ycls[0][y]*nx0, a1 = S->ycls[0][y+1]*nx0;
            int b0 = S->xcls[0][x],     b1 = S->xcls[0][x+1];
            c0[0]=a0+b0; c0[1]=a0+b1; c0[2]=a1+b0; c0[3]=a1+b1;
        }
        {
            int a0 = S->ycls[1][y]*nx1, a1 = S->ycls[1][y+1]*nx1;
            int b0 = S->xcls[1][x],     b1 = S->xcls[1][x+1];
            c1[0]=a0+b0; c1[1]=a0+b1; c1[2]=a1+b0; c1[3]=a1+b1;
        }
        float* outp = g_x1 + (size_t)n * X1_PER_PAIR + pix;
#pragma unroll 8
        for (int co = 0; co < 64; ++co) {
            const float* T0 = S->T[0] + co*128;
            const float* T1 = S->T[1] + co*128;
            float v0 = T0[c0[0]] + T1[c1[0]];
            float v1 = T0[c0[1]] + T1[c1[1]];
            float v2 = T0[c0[2]] + T1[c1[2]];
            float v3 = T0[c0[3]] + T1[c1[3]];
            float best = fmaxf(fmaxf(v0, v1), fmaxf(v2, v3));
            outp[co * 900] = best + S->sB[co];
        }
    }
}

// ---------------------------------------------------------------------------
// Kernel 3: conv2 + bias-free accumulate + maxpool2 + mean. One block per pair.
// 384 threads: tid -> cog = tid&3 (8 co each), slot = tid>>2 (0..90 active):
// yp = slot/7 (y-pair rows yp, yp+13), xg = slot%7 (x0 = 4*xg, 4 outputs).
// acc[4][8] f32x2. Inputs: per (ci,dy) 6 LDS.128 -> 9 packed f32x2 reused
// over dx. Weights: 8 LDS.64 per tap, amortized over 4 x-outputs.
// ---------------------------------------------------------------------------
#define CI_CHUNK 16
#define IN_ROW 36                                   // floats (144B, 16B-aligned rows)
#define SIN_FLOATS (CI_CHUNK * 30 * IN_ROW)         // 17280 floats = 69120 B
#define W_ROW 33                                    // u64 stride per tap
#define SW_U64 (CI_CHUNK * 25 * W_ROW)              // 13200 u64 = 105600 B
#define SMEM3_BYTES (SIN_FLOATS*4 + SW_U64*8)       // 174720 B

__global__ void __launch_bounds__(384, 1)
k_conv2(const float* __restrict__ conv2_w, const float* __restrict__ conv2_b) {
    extern __shared__ float sm[];
    float* s_in = sm;                                // [cil][30][36]
    u64*   s_w  = (u64*)(sm + SIN_FLOATS);           // [cil*25+k][33] {w,w}

    int n = blockIdx.x, tid = threadIdx.x;
    int cog  = tid & 3;
    int slot = tid >> 2;
    bool act = slot < 91;
    int sl = act ? slot : 0;
    int yp = sl / 7, xg = sl - yp * 7;
    int x0 = xg * 4;

    u64 acc[4][8];
#pragma unroll
    for (int k = 0; k < 4; ++k)
#pragma unroll
        for (int c = 0; c < 8; ++c) acc[k][c] = 0ull;

    const float* gsrc = g_x1 + (size_t)n * X1_PER_PAIR;

    for (int ci0 = 0; ci0 < 64; ci0 += CI_CHUNK) {
        __syncthreads();
        // stage input (coalesced gmem, padded rows in smem)
        for (int i = tid; i < CI_CHUNK * 900; i += 384) {
            int ci = i / 900, p = i - ci * 900;
            int r = p / 30, c = p - r * 30;
            s_in[ci * (30*IN_ROW) + r * IN_ROW + c] = gsrc[ci0 * 900 + i];
        }
        // stage weights packed {w,w}; coalesced gmem per co
        for (int i = tid; i < 32 * CI_CHUNK * 25; i += 384) {
            int co  = i / (CI_CHUNK * 25);
            int rem = i - co * (CI_CHUNK * 25);        // cil*25+k
            float w = conv2_w[co * 1600 + ci0 * 25 + rem];
            s_w[rem * W_ROW + co] = pack2(w, w);
        }
        __syncthreads();

        for (int cil = 0; cil < CI_CHUNK; ++cil) {
            const float* ib = s_in + cil * (30*IN_ROW);
            const u64*   wb = s_w + cil * 25 * W_ROW;
#pragma unroll 1
            for (int dy = 0; dy < 5; ++dy) {
                const float4* rA = (const float4*)(ib + (yp + dy)      * IN_ROW + x0);
                const float4* rB = (const float4*)(ib + (yp + 13 + dy) * IN_ROW + x0);
                float4 a0 = rA[0], a1 = rA[1], a2 = rA[2];
                float4 b0 = rB[0], b1 = rB[1], b2 = rB[2];
                u64 in2[9];
                in2[0] = pack2(a0.x, b0.x); in2[1] = pack2(a0.y, b0.y);
                in2[2] = pack2(a0.z, b0.z); in2[3] = pack2(a0.w, b0.w);
                in2[4] = pack2(a1.x, b1.x); in2[5] = pack2(a1.y, b1.y);
                in2[6] = pack2(a1.z, b1.z); in2[7] = pack2(a1.w, b1.w);
                in2[8] = pack2(a2.x, b2.x);
#pragma unroll
                for (int dx = 0; dx < 5; ++dx) {
                    const u64* wp = wb + (dy * 5 + dx) * W_ROW + cog * 8;
                    u64 w0=wp[0], w1=wp[1], w2=wp[2], w3=wp[3],
                        w4=wp[4], w5=wp[5], w6=wp[6], w7=wp[7];
#pragma unroll
                    for (int k = 0; k < 4; ++k) {
                        u64 v = in2[k + dx];
                        fma2(acc[k][0], w0, v); fma2(acc[k][1], w1, v);
                        fma2(acc[k][2], w2, v); fma2(acc[k][3], w3, v);
                        fma2(acc[k][4], w4, v); fma2(acc[k][5], w5, v);
                        fma2(acc[k][6], w6, v); fma2(acc[k][7], w7, v);
                    }
                }
            }
        }
    }
    __syncthreads();

    // Epilogue: stage conv out, maxpool 26->13, mean, +bias.
    float* s_out  = sm;                      // [32][680]
    float* s_pool = sm + 32 * 680;           // [32][169]
    if (act) {
#pragma unroll
        for (int c = 0; c < 8; ++c) {
            int co = cog * 8 + c;
#pragma unroll
            for (int k = 0; k < 4; ++k) {
                int x = x0 + k;
                if (x < 26) {
                    float lo, hi; unpack2(lo, hi, acc[k][c]);
                    s_out[co * 680 + yp * 26 + x]        = lo;
                    s_out[co * 680 + (yp + 13) * 26 + x] = hi;
                }
            }
        }
    }
    __syncthreads();
    for (int i = tid; i < 32 * 169; i += 384) {
        int co = i / 169, q = i - co * 169;
        int qy = q / 13, qx = q - qy * 13;
        const float* o = s_out + co * 680 + qy * 52 + qx * 2;
        s_pool[i] = fmaxf(fmaxf(o[0], o[1]), fmaxf(o[26], o[27]));
    }
    __syncthreads();
    if (tid < 32) {
        const float* pp = s_pool + tid * 169;
        float s = 0.f;
#pragma unroll 13
        for (int q = 0; q < 169; ++q) s += pp[q];
        g_feat[n * 32 + tid] = s * (1.0f / 169.0f) + conv2_b[tid];
    }
}

// ---------------------------------------------------------------------------
// Kernel 4: fc (32->512) + relu, 8 pairs per block.
// ---------------------------------------------------------------------------
__global__ void __launch_bounds__(512)
k_fc(const float* __restrict__ fc_w, const float* __restrict__ fc_b,
     float* __restrict__ out) {
    __shared__ float sf[8][32];
    int nb = blockIdx.x * 8, tid = threadIdx.x;
    if (tid < 256) {
        int j = tid >> 5, k = tid & 31;
        sf[j][k] = g_feat[(nb + j) * 32 + k];
    }
    __syncthreads();
    float w[32];
    const float* wr = fc_w + tid * 32;
#pragma unroll
    for (int k = 0; k < 32; ++k) w[k] = wr[k];
    float b = fc_b[tid];
#pragma unroll
    for (int j = 0; j < 8; ++j) {
        float s = b;
#pragma unroll
        for (int k = 0; k < 32; ++k) s += sf[j][k] * w[k];
        out[(size_t)(nb + j) * 512 + tid] = fmaxf(s, 0.f);
    }
}

// ---------------------------------------------------------------------------
extern "C" void kernel_launch(void* const* d_in, const int* in_sizes, int n_in,
                              void* d_out, int out_size) {
    const float* bboxes  = (const float*)d_in[0];
    const int*   pairs   = (const int*)  d_in[3];
    const float* conv1_w = (const float*)d_in[4];
    const float* conv1_b = (const float*)d_in[5];
    const float* conv2_w = (const float*)d_in[6];
    const float* conv2_b = (const float*)d_in[7];
    const float* fc_w    = (const float*)d_in[8];
    const float* fc_b    = (const float*)d_in[9];
    float* out = (float*)d_out;

    cudaFuncSetAttribute(k_sp_conv1, cudaFuncAttributeMaxDynamicSharedMemorySize, SP_SMEM);
    cudaFuncSetAttribute(k_conv2, cudaFuncAttributeMaxDynamicSharedMemorySize, SMEM3_BYTES);

    k_prefix  <<<1, 128>>>(conv1_w);
    k_sp_conv1<<<NPAIR, 256, SP_SMEM>>>(bboxes, pairs, conv1_b);
    k_conv2   <<<NPAIR, 384, SMEM3_BYTES>>>(conv2_w, conv2_b);
    k_fc      <<<NPAIR/8, 512>>>(fc_w, fc_b, out);
}

// round 9
// speedup vs baseline: 2.8721x; 2.8721x over previous
#include <cuda_runtime.h>
#include <cuda_bf16.h>
#include <cstdint>

// ---------------------------------------------------------------------------
// B=16, R=64, NOBJ=32, SIZE=64
//   conv1(2->64,5x5)+pool2 -> bf16 hi/lo channel-last  [prefix-sum + classes]
//   conv2(64->32,5x5)+pool2+mean -> g_feat             [mma.sync bf16 3-term]
//   fc(32->512)+relu -> out
// Harness compiles generic compute_103 PTX: tcgen05 unusable, f32x2 lowered
// to scalar FFMA. mma.sync (sm_80 ISA) IS available -> use the tensor pipe.
// ---------------------------------------------------------------------------

#define NPAIR 1024
typedef unsigned long long u64;
typedef uint32_t u32;
typedef unsigned short u16;

__device__ float g_P[64*2*36];                 // conv1 weight prefix sums
__device__ uint4 g_hi4[(size_t)NPAIR*900*8];   // conv1 out bf16 hi [n][pix][64ci]
__device__ uint4 g_lo4[(size_t)NPAIR*900*8];   // conv1 out bf16 lo
__device__ uint4 g_wb4[19200];                 // conv2 W [chunk4][term2][tap25][co32][48B]
__device__ float g_feat[NPAIR * 32];

// ---------------------------------------------------------------------------
// Kernel 1: 2-D prefix sums of conv1 weights.
// ---------------------------------------------------------------------------
__global__ void k_prefix(const float* __restrict__ conv1_w) {
    int t = threadIdx.x;
    if (t >= 128) return;
    const float* w = conv1_w + t * 25;
    float P[6][6];
#pragma unroll
    for (int i = 0; i < 6; ++i) { P[0][i] = 0.f; P[i][0] = 0.f; }
#pragma unroll
    for (int j = 1; j <= 5; ++j)
#pragma unroll
        for (int i = 1; i <= 5; ++i)
            P[j][i] = w[(j-1)*5 + (i-1)] + P[j-1][i] + P[j][i-1] - P[j-1][i-1];
#pragma unroll
    for (int j = 0; j < 6; ++j)
#pragma unroll
        for (int i = 0; i < 6; ++i)
            g_P[t*36 + j*6 + i] = P[j][i];
}

// ---------------------------------------------------------------------------
// Kernel 1b: conv2 weights -> bf16 hi/lo in mma-B-friendly padded layout.
// Byte layout: ((chunk*2+term)*25 + tap)*1536 + co*48 + k*2,  k=ci&15.
// ---------------------------------------------------------------------------
__global__ void k_prepw(const float* __restrict__ conv2_w) {
    int i = blockIdx.x * 256 + threadIdx.x;
    if (i >= 51200) return;
    int co = i / 1600, rem = i - co * 1600, ci = rem / 25, tap = rem - ci * 25;
    float w = conv2_w[i];
    __nv_bfloat16 bh = __float2bfloat16(w);
    __nv_bfloat16 bl = __float2bfloat16(w - __bfloat162float(bh));
    int chunk = ci >> 4, k = ci & 15;
    char* base = (char*)g_wb4;
    *(u16*)(base + ((size_t)(chunk*2 + 0)*25 + tap)*1536 + co*48 + k*2) =
        __bfloat16_as_ushort(bh);
    *(u16*)(base + ((size_t)(chunk*2 + 1)*25 + tap)*1536 + co*48 + k*2) =
        __bfloat16_as_ushort(bl);
}

// ---------------------------------------------------------------------------
// Kernel 2: sp + conv1 + bias + maxpool2 via clamp classes; writes bf16
// hi/lo channel-last [n][pix][64].
// ---------------------------------------------------------------------------
#define MAXCLS 16
struct SpShm {
    float sP[4608];
    float T[2][64*128];
    float sB[64];
    int   xcls[2][64], ycls[2][64];
    int   xpl[2][MAXCLS], xph[2][MAXCLS];
    int   ypl[2][MAXCLS], yph[2][MAXCLS];
    int   nx[2], ny[2];
    int   rxlo[2], rxhi[2], rylo[2], ryhi[2];
};
#define SP_SMEM ((int)sizeof(SpShm))

__global__ void __launch_bounds__(256, 2)
k_sp_conv1(const float* __restrict__ bboxes,
           const int*   __restrict__ pairs,
           const float* __restrict__ conv1_b) {
    extern __shared__ char smraw[];
    SpShm* S = (SpShm*)smraw;

    int n = blockIdx.x, tid = threadIdx.x;
    for (int i = tid; i < 4608; i += 256) S->sP[i] = g_P[i];
    if (tid < 64) S->sB[tid] = conv1_b[tid];

    if (tid == 0) {
        int b = n >> 6, r = n & 63;
        int o0 = pairs[(b*64 + r)*2 + 0];
        int o1 = pairs[(b*64 + r)*2 + 1];
        const float* A  = bboxes + ((size_t)b*32 + o0)*4;
        const float* Bx = bboxes + ((size_t)b*32 + o1)*4;
        float ux1 = fminf(A[0], Bx[0]), uy1 = fminf(A[1], Bx[1]);
        float ux2 = fmaxf(A[2], Bx[2]), uy2 = fmaxf(A[3], Bx[3]);
        float uw = fmaxf(ux2 - ux1, 1e-6f), uh = fmaxf(uy2 - uy1, 1e-6f);
        const float* bx[2] = {A, Bx};
#pragma unroll
        for (int ci = 0; ci < 2; ++ci) {
            float x1 = (bx[ci][0] - ux1) / uw * 64.0f;
            float y1 = (bx[ci][1] - uy1) / uh * 64.0f;
            float x2 = (bx[ci][2] - ux1) / uw * 64.0f;
            float y2 = (bx[ci][3] - uy1) / uh * 64.0f;
            S->rxlo[ci] = max(0,  (int)ceilf (x1 - 0.5f));
            S->rxhi[ci] = min(63, (int)floorf(x2 - 0.5f));
            S->rylo[ci] = max(0,  (int)ceilf (y1 - 0.5f));
            S->ryhi[ci] = min(63, (int)floorf(y2 - 0.5f));
        }
    }
    __syncthreads();

    if (tid < 4) {
        int ci = tid >> 1, ax = tid & 1;
        int rlo = ax ? S->rylo[ci] : S->rxlo[ci];
        int rhi = ax ? S->ryhi[ci] : S->rxhi[ci];
        int* cls  = ax ? S->ycls[ci] : S->xcls[ci];
        int* lstL = ax ? S->ypl[ci]  : S->xpl[ci];
        int* lstH = ax ? S->yph[ci]  : S->xph[ci];
        int keys[MAXCLS];
        int nc = 0;
        for (int v = 0; v < 60; ++v) {
            int lo = max(0, rlo - v), hi = min(4, rhi - v);
            int key = (hi >= lo) ? (lo * 6 + hi) : 99;
            int id = -1;
            for (int j = 0; j < nc; ++j) if (keys[j] == key) { id = j; break; }
            if (id < 0) {
                id = nc; keys[nc] = key;
                lstL[nc] = (hi >= lo) ? lo : 1;
                lstH[nc] = (hi >= lo) ? hi : 0;
                ++nc;
            }
            cls[v] = id;
        }
        if (ax) S->ny[ci] = nc; else S->nx[ci] = nc;
    }
    __syncthreads();

#pragma unroll
    for (int ci = 0; ci < 2; ++ci) {
        int nxv = S->nx[ci], nyv = S->ny[ci];
        int ncls = nxv * nyv, tot = 64 * ncls;
        for (int i = tid; i < tot; i += 256) {
            int co = i / ncls, c = i - co * ncls;
            int cy = c / nxv, cx = c - cy * nxv;
            int xl = S->xpl[ci][cx], xh = S->xph[ci][cx];
            int yl = S->ypl[ci][cy], yh = S->yph[ci][cy];
            float v = 0.f;
            if (xh >= xl && yh >= yl) {
                const float* P = S->sP + (co*2 + ci)*36;
                v = P[(yh+1)*6 + (xh+1)] - P[yl*6 + (xh+1)]
                  - P[(yh+1)*6 + xl]     + P[yl*6 + xl];
            }
            S->T[ci][co*128 + c] = v;
        }
    }
    __syncthreads();

    int nx0 = S->nx[0], nx1 = S->nx[1];
    for (int pix = tid; pix < 900; pix += 256) {
        int py = pix / 30, px = pix - py*30;
        int y = 2*py, x = 2*px;
        int c0[4], c1[4];
        {
            int a0 = S->ycls[0][y]*nx0, a1 = S->ycls[0][y+1]*nx0;
            int b0 = S->xcls[0][x],     b1 = S->xcls[0][x+1];
            c0[0]=a0+b0; c0[1]=a0+b1; c0[2]=a1+b0; c0[3]=a1+b1;
        }
        {
            int a0 = S->ycls[1][y]*nx1, a1 = S->ycls[1][y+1]*nx1;
            int b0 = S->xcls[1][x],     b1 = S->xcls[1][x+1];
            c1[0]=a0+b0; c1[1]=a0+b1; c1[2]=a1+b0; c1[3]=a1+b1;
        }
        size_t obase = ((size_t)n*900 + pix) * 8;
#pragma unroll
        for (int hf = 0; hf < 2; ++hf) {
            u32 hb[16], lb[16];
#pragma unroll 8
            for (int j = 0; j < 32; ++j) {
                int co = hf*32 + j;
                const float* T0 = S->T[0] + co*128;
                const float* T1 = S->T[1] + co*128;
                float v0 = T0[c0[0]] + T1[c1[0]];
                float v1 = T0[c0[1]] + T1[c1[1]];
                float v2 = T0[c0[2]] + T1[c1[2]];
                float v3 = T0[c0[3]] + T1[c1[3]];
                float val = fmaxf(fmaxf(v0, v1), fmaxf(v2, v3)) + S->sB[co];
                __nv_bfloat16 bh = __float2bfloat16(val);
                __nv_bfloat16 blv = __float2bfloat16(val - __bfloat162float(bh));
                u16 uh = __bfloat16_as_ushort(bh), ul = __bfloat16_as_ushort(blv);
                if (j & 1) { hb[j>>1] |= (u32)uh << 16; lb[j>>1] |= (u32)ul << 16; }
                else       { hb[j>>1]  = uh;            lb[j>>1]  = ul; }
            }
            uint4* oh = g_hi4 + obase + hf*4;
            uint4* ol = g_lo4 + obase + hf*4;
#pragma unroll
            for (int q = 0; q < 4; ++q) {
                oh[q] = make_uint4(hb[4*q], hb[4*q+1], hb[4*q+2], hb[4*q+3]);
                ol[q] = make_uint4(lb[4*q], lb[4*q+1], lb[4*q+2], lb[4*q+3]);
            }
        }
    }
}

// ---------------------------------------------------------------------------
// Kernel 3: conv2 via mma.sync.m16n8k16 bf16, 3-term compensation.
// One block per pair, 256 threads (8 warps). GEMM: M=676 (26x26), N=32,
// K=1600 as 4 ci-chunks x 25 taps (k16 each). Image smem: [pix900][48B]
// (16 bf16 + pad) per hi/lo plane, conflict-free fragment loads.
// Warp w owns m-tiles w*6..w*6+5 (43 used). acc[6][4][4] fp32.
// ---------------------------------------------------------------------------
#define IMG_PLANE 43200                     // 900*48
#define W_BYTES   76800                     // 2*25*32*48
#define CONV2_SMEM (2*IMG_PLANE + W_BYTES)  // 163200

__device__ __forceinline__ void mma16816(float* c, u32 a0, u32 a1, u32 a2, u32 a3,
                                         u32 b0, u32 b1) {
    asm volatile("mma.sync.aligned.m16n8k16.row.col.f32.bf16.bf16.f32 "
                 "{%0,%1,%2,%3}, {%4,%5,%6,%7}, {%8,%9}, {%0,%1,%2,%3};"
                 : "+f"(c[0]), "+f"(c[1]), "+f"(c[2]), "+f"(c[3])
                 : "r"(a0), "r"(a1), "r"(a2), "r"(a3), "r"(b0), "r"(b1));
}

__global__ void __launch_bounds__(256, 1)
k_conv2mma(const float* __restrict__ conv2_b) {
    extern __shared__ char sm[];
    char* s_hi = sm;
    char* s_lo = sm + IMG_PLANE;
    char* s_w  = sm + 2*IMG_PLANE;

    int n = blockIdx.x, tid = threadIdx.x;
    int w = tid >> 5, lane = tid & 31;
    int g = lane >> 2, tig = lane & 3;

    // m-tile pixel bases (byte offsets into image planes) per warp
    int base0[6], base1[6];
    bool v0[6], v1[6];
#pragma unroll
    for (int i = 0; i < 6; ++i) {
        int mt = w * 6 + i;
        int p0 = mt * 16 + g, p1 = p0 + 8;
        v0[i] = (mt < 43) && (p0 < 676);
        v1[i] = (mt < 43) && (p1 < 676);
        int pc0 = v0[i] ? p0 : 0, pc1 = v1[i] ? p1 : 0;
        int y0 = pc0 / 26, x0 = pc0 - y0 * 26;
        int y1 = pc1 / 26, x1 = pc1 - y1 * 26;
        base0[i] = (y0 * 30 + x0) * 48 + tig * 4;
        base1[i] = (y1 * 30 + x1) * 48 + tig * 4;
    }

    float acc[6][4][4];
#pragma unroll
    for (int i = 0; i < 6; ++i)
#pragma unroll
        for (int nt = 0; nt < 4; ++nt)
#pragma unroll
            for (int q = 0; q < 4; ++q) acc[i][nt][q] = 0.f;

    for (int chunk = 0; chunk < 4; ++chunk) {
        __syncthreads();
        // stage image chunk: 2 uint4 per pixel per plane at 48B stride
        {
            const uint4* ghi = g_hi4 + (size_t)n * 7200 + chunk * 2;
            const uint4* glo = g_lo4 + (size_t)n * 7200 + chunk * 2;
            for (int i = tid; i < 1800; i += 256) {
                int p = i >> 1, j = i & 1;
                uint4 vh = ghi[p * 8 + j];
                uint4 vl = glo[p * 8 + j];
                *(uint4*)(s_hi + p * 48 + j * 16) = vh;
                *(uint4*)(s_lo + p * 48 + j * 16) = vl;
            }
        }
        // stage weight chunk (flat copy)
        {
            const uint4* wsrc = g_wb4 + chunk * 4800;
            uint4* wdst = (uint4*)s_w;
            for (int i = tid; i < 4800; i += 256) wdst[i] = wsrc[i];
        }
        __syncthreads();

        for (int tap = 0; tap < 25; ++tap) {
            int dy = tap / 5, dx = tap - dy * 5;
            int toff = (dy * 30 + dx) * 48;
            // B fragments: 4 n-tiles x {hi,lo}
            u32 bh[4][2], bl[4][2];
            const char* wt = s_w + tap * 1536;
#pragma unroll
            for (int nt = 0; nt < 4; ++nt) {
                int co = nt * 8 + g;
                bh[nt][0] = *(const u32*)(wt + co * 48 + tig * 4);
                bh[nt][1] = *(const u32*)(wt + co * 48 + tig * 4 + 16);
                bl[nt][0] = *(const u32*)(wt + 38400 + co * 48 + tig * 4);
                bl[nt][1] = *(const u32*)(wt + 38400 + co * 48 + tig * 4 + 16);
            }
#pragma unroll
            for (int i = 0; i < 6; ++i) {
                int o0 = base0[i] + toff, o1 = base1[i] + toff;
                u32 ah0 = *(const u32*)(s_hi + o0);
                u32 ah1 = *(const u32*)(s_hi + o1);
                u32 ah2 = *(const u32*)(s_hi + o0 + 16);
                u32 ah3 = *(const u32*)(s_hi + o1 + 16);
                u32 al0 = *(const u32*)(s_lo + o0);
                u32 al1 = *(const u32*)(s_lo + o1);
                u32 al2 = *(const u32*)(s_lo + o0 + 16);
                u32 al3 = *(const u32*)(s_lo + o1 + 16);
#pragma unroll
                for (int nt = 0; nt < 4; ++nt) {
                    mma16816(acc[i][nt], ah0, ah1, ah2, ah3, bh[nt][0], bh[nt][1]);
                    mma16816(acc[i][nt], ah0, ah1, ah2, ah3, bl[nt][0], bl[nt][1]);
                    mma16816(acc[i][nt], al0, al1, al2, al3, bh[nt][0], bh[nt][1]);
                }
            }
        }
    }
    __syncthreads();

    // Epilogue: fragments -> s_out[pix][32co], pool 26->13, mean, +bias.
    float* s_out  = (float*)sm;                 // 676*32*4 = 86528 B
    float* s_pool = (float*)(sm + 86528);       // 32*169*4 = 21632 B
#pragma unroll
    for (int i = 0; i < 6; ++i) {
        int mt = w * 6 + i;
        int p0 = mt * 16 + g, p1 = p0 + 8;
#pragma unroll
        for (int nt = 0; nt < 4; ++nt) {
            int co = nt * 8 + tig * 2;
            if (v0[i]) {
                s_out[p0 * 32 + co]     = acc[i][nt][0];
                s_out[p0 * 32 + co + 1] = acc[i][nt][1];
            }
            if (v1[i]) {
                s_out[p1 * 32 + co]     = acc[i][nt][2];
                s_out[p1 * 32 + co + 1] = acc[i][nt][3];
            }
        }
    }
    __syncthreads();
    for (int i = tid; i < 32 * 169; i += 256) {
        int co = i / 169, q = i - co * 169;
        int qy = q / 13, qx = q - qy * 13;
        const float* o = s_out + (qy * 52 + qx * 2) * 32 + co;
        s_pool[co * 169 + q] =
            fmaxf(fmaxf(o[0], o[32]), fmaxf(o[26*32], o[27*32]));
    }
    __syncthreads();
    if (tid < 32) {
        const float* pp = s_pool + tid * 169;
        float s = 0.f;
#pragma unroll 13
        for (int q = 0; q < 169; ++q) s += pp[q];
        g_feat[n * 32 + tid] = s * (1.0f / 169.0f) + conv2_b[tid];
    }
}

// ---------------------------------------------------------------------------
// Kernel 4: fc (32->512) + relu, 8 pairs per block.
// ---------------------------------------------------------------------------
__global__ void __launch_bounds__(512)
k_fc(const float* __restrict__ fc_w, const float* __restrict__ fc_b,
     float* __restrict__ out) {
    __shared__ float sf[8][32];
    int nb = blockIdx.x * 8, tid = threadIdx.x;
    if (tid < 256) {
        int j = tid >> 5, k = tid & 31;
        sf[j][k] = g_feat[(nb + j) * 32 + k];
    }
    __syncthreads();
    float w[32];
    const float* wr = fc_w + tid * 32;
#pragma unroll
    for (int k = 0; k < 32; ++k) w[k] = wr[k];
    float b = fc_b[tid];
#pragma unroll
    for (int j = 0; j < 8; ++j) {
        float s = b;
#pragma unroll
        for (int k = 0; k < 32; ++k) s += sf[j][k] * w[k];
        out[(size_t)(nb + j) * 512 + tid] = fmaxf(s, 0.f);
    }
}

// ---------------------------------------------------------------------------
extern "C" void kernel_launch(void* const* d_in, const int* in_sizes, int n_in,
                              void* d_out, int out_size) {
    const float* bboxes  = (const float*)d_in[0];
    const int*   pairs   = (const int*)  d_in[3];
    const float* conv1_w = (const float*)d_in[4];
    const float* conv1_b = (const float*)d_in[5];
    const float* conv2_w = (const float*)d_in[6];
    const float* conv2_b = (const float*)d_in[7];
    const float* fc_w    = (const float*)d_in[8];
    const float* fc_b    = (const float*)d_in[9];
    float* out = (float*)d_out;

    cudaFuncSetAttribute(k_sp_conv1, cudaFuncAttributeMaxDynamicSharedMemorySize, SP_SMEM);
    cudaFuncSetAttribute(k_conv2mma, cudaFuncAttributeMaxDynamicSharedMemorySize, CONV2_SMEM);

    k_prefix  <<<1, 128>>>(conv1_w);
    k_prepw   <<<200, 256>>>(conv2_w);
    k_sp_conv1<<<NPAIR, 256, SP_SMEM>>>(bboxes, pairs, conv1_b);
    k_conv2mma<<<NPAIR, 256, CONV2_SMEM>>>(conv2_b);
    k_fc      <<<NPAIR/8, 512>>>(fc_w, fc_b, out);
}